// round 16
// baseline (speedup 1.0000x reference)
#include <cuda_runtime.h>
#include <cuda_bf16.h>
#include <cuda_fp16.h>
#include <mma.h>
#include <cstdint>

using namespace nvcuda;

// Problem constants
constexpr int kB = 2;
constexpr int kT = 2048;
constexpr int kC = 1024;
constexpr int kH = 16;
constexpr int kD = 64;
constexpr int kM = kB * kT;        // 4096
constexpr int kNQKV = 3 * kC;      // 3072
constexpr int kBH = kB * kH;       // 32

// Scratch (static device globals — no allocation allowed)
__device__ float g_qkv[kM * kNQKV];
__device__ __half g_qf[kBH * kT * kD];
__device__ __half g_kf[kBH * kT * kD];
__device__ __half g_vf[kBH * kT * kD];
// fp16 QKV-GEMM operands
__device__ __half g_xf[kM * kC];
__device__ __half g_wqf[kNQKV * kC];
// split-bf16 out-proj operands
__device__ __nv_bfloat16 g_ath[kM * kC], g_atl[kM * kC];
__device__ __nv_bfloat16 g_woh[kC * kC], g_wol[kC * kC];

// ===========================================================================
// helpers
// ===========================================================================
__device__ __forceinline__ uint32_t smem_u32(const void* p) {
    uint32_t a;
    asm("{ .reg .u64 t; cvta.to.shared.u64 t, %1; cvt.u32.u64 %0, t; }"
        : "=r"(a) : "l"(p));
    return a;
}
__device__ __forceinline__ void cp_async16(void* sdst, const void* gsrc) {
    asm volatile("cp.async.cg.shared.global [%0], [%1], 16;"
                 :: "r"(smem_u32(sdst)), "l"(gsrc) : "memory");
}
__device__ __forceinline__ void cp_commit() {
    asm volatile("cp.async.commit_group;" ::: "memory");
}
__device__ __forceinline__ void cp_wait0() {
    asm volatile("cp.async.wait_group 0;" ::: "memory");
}
__device__ __forceinline__ void cp_wait1() {
    asm volatile("cp.async.wait_group 1;" ::: "memory");
}
__device__ __forceinline__ void cp_wait2() {
    asm volatile("cp.async.wait_group 2;" ::: "memory");
}
__device__ __forceinline__ float fast_exp2(float x) {
    float y;
    asm("ex2.approx.ftz.f32 %0, %1;" : "=f"(y) : "f"(x));
    return y;
}

// ===========================================================================
// Single-pass FP16 GEMM-NT via WMMA (QKV projection). Round-13 proven.
// ===========================================================================
constexpr int kLds = 40;
constexpr int kStageElems = 2 * 128 * kLds;
constexpr int kGemmSmem16 = 4 * kStageElems * 2;

__global__ __launch_bounds__(256) void gemm_wmma_fp16(
    const __half* __restrict__ A, const __half* __restrict__ Bm,
    float* __restrict__ Cm, int Nd, int Kd)
{
    extern __shared__ __half smh[];

    const int tid = threadIdx.x;
    const int warp = tid >> 5;
    const int wm = warp & 3;
    const int wn = warp >> 2;
    const int row0 = blockIdx.y * 128;
    const int col0 = blockIdx.x * 128;

    const int nchunk = Kd >> 5;

    auto issue = [&](int it) {
        const int kc = it << 5;
        __half* As = smh + (it & 3) * kStageElems;
        __half* Bs = As + 128 * kLds;
#pragma unroll
        for (int s = 0; s < 2; s++) {
            int idx = tid + s * 256;
            int r = idx >> 2;
            int c8 = (idx & 3) * 8;
            cp_async16(&As[r * kLds + c8], A + (size_t)(row0 + r) * Kd + kc + c8);
            cp_async16(&Bs[r * kLds + c8], Bm + (size_t)(col0 + r) * Kd + kc + c8);
        }
    };

    wmma::fragment<wmma::accumulator, 16, 16, 16, float> acc[2][4];
#pragma unroll
    for (int i = 0; i < 2; i++)
#pragma unroll
        for (int j = 0; j < 4; j++)
            wmma::fill_fragment(acc[i][j], 0.f);

    issue(0); cp_commit();
    issue(1); cp_commit();
    issue(2); cp_commit();

    for (int it = 0; it < nchunk; it++) {
        cp_wait2();
        __syncthreads();
        if (it + 3 < nchunk) issue(it + 3);
        cp_commit();

        const __half* As = smh + (it & 3) * kStageElems;
        const __half* Bs = As + 128 * kLds;
#pragma unroll
        for (int k2 = 0; k2 < 2; k2++) {
            wmma::fragment<wmma::matrix_a, 16, 16, 16, __half,
                           wmma::row_major> af[2];
            wmma::fragment<wmma::matrix_b, 16, 16, 16, __half,
                           wmma::col_major> bf[4];
#pragma unroll
            for (int i = 0; i < 2; i++)
                wmma::load_matrix_sync(
                    af[i], &As[(wm * 32 + i * 16) * kLds + k2 * 16], kLds);
#pragma unroll
            for (int j = 0; j < 4; j++)
                wmma::load_matrix_sync(
                    bf[j], &Bs[(wn * 64 + j * 16) * kLds + k2 * 16], kLds);
#pragma unroll
            for (int i = 0; i < 2; i++)
#pragma unroll
                for (int j = 0; j < 4; j++)
                    wmma::mma_sync(acc[i][j], af[i], bf[j], acc[i][j]);
        }
    }

#pragma unroll
    for (int i = 0; i < 2; i++)
#pragma unroll
        for (int j = 0; j < 4; j++) {
            float* cp = Cm + (size_t)(row0 + wm * 32 + i * 16) * Nd
                           + col0 + wn * 64 + j * 16;
            wmma::store_matrix_sync(cp, acc[i][j], Nd, wmma::mem_row_major);
        }
}

// ===========================================================================
// 3-pass split-bf16 GEMM-NT via WMMA (round-5 proven) — out-projection.
// ===========================================================================
constexpr int kGemmSmemBf = 4 * kStageElems * 2;

__global__ __launch_bounds__(256) void gemm_wmma_split(
    const __nv_bfloat16* __restrict__ Ah, const __nv_bfloat16* __restrict__ Al,
    const __nv_bfloat16* __restrict__ Bh, const __nv_bfloat16* __restrict__ Bl,
    float* __restrict__ Cm, int Nd, int Kd)
{
    extern __shared__ __nv_bfloat16 sm[];

    const int tid = threadIdx.x;
    const int warp = tid >> 5;
    const int wm = warp & 3;
    const int wn = warp >> 2;
    const int row0 = blockIdx.y * 128;
    const int col0 = blockIdx.x * 128;

    const int nchunk = Kd >> 5;
    const int total = 3 * nchunk;

    auto issue = [&](int it) {
        const int pass = it / nchunk;
        const int kc = (it - pass * nchunk) << 5;
        const __nv_bfloat16* Ap = (pass == 2) ? Al : Ah;
        const __nv_bfloat16* Bp = (pass == 1) ? Bl : Bh;
        __nv_bfloat16* As = sm + (it & 3) * kStageElems;
        __nv_bfloat16* Bs = As + 128 * kLds;
#pragma unroll
        for (int s = 0; s < 2; s++) {
            int idx = tid + s * 256;
            int r = idx >> 2;
            int c8 = (idx & 3) * 8;
            cp_async16(&As[r * kLds + c8], Ap + (size_t)(row0 + r) * Kd + kc + c8);
            cp_async16(&Bs[r * kLds + c8], Bp + (size_t)(col0 + r) * Kd + kc + c8);
        }
    };

    wmma::fragment<wmma::accumulator, 16, 16, 16, float> acc[2][4];
#pragma unroll
    for (int i = 0; i < 2; i++)
#pragma unroll
        for (int j = 0; j < 4; j++)
            wmma::fill_fragment(acc[i][j], 0.f);

    issue(0); cp_commit();
    issue(1); cp_commit();
    issue(2); cp_commit();

    for (int it = 0; it < total; it++) {
        cp_wait2();
        __syncthreads();
        if (it + 3 < total) issue(it + 3);
        cp_commit();

        const __nv_bfloat16* As = sm + (it & 3) * kStageElems;
        const __nv_bfloat16* Bs = As + 128 * kLds;
#pragma unroll
        for (int k2 = 0; k2 < 2; k2++) {
            wmma::fragment<wmma::matrix_a, 16, 16, 16, __nv_bfloat16,
                           wmma::row_major> af[2];
            wmma::fragment<wmma::matrix_b, 16, 16, 16, __nv_bfloat16,
                           wmma::col_major> bf[4];
#pragma unroll
            for (int i = 0; i < 2; i++)
                wmma::load_matrix_sync(
                    af[i], &As[(wm * 32 + i * 16) * kLds + k2 * 16], kLds);
#pragma unroll
            for (int j = 0; j < 4; j++)
                wmma::load_matrix_sync(
                    bf[j], &Bs[(wn * 64 + j * 16) * kLds + k2 * 16], kLds);
#pragma unroll
            for (int i = 0; i < 2; i++)
#pragma unroll
                for (int j = 0; j < 4; j++)
                    wmma::mma_sync(acc[i][j], af[i], bf[j], acc[i][j]);
        }
    }

#pragma unroll
    for (int i = 0; i < 2; i++)
#pragma unroll
        for (int j = 0; j < 4; j++) {
            float* cp = Cm + (size_t)(row0 + wm * 32 + i * 16) * Nd
                           + col0 + wn * 64 + j * 16;
            wmma::store_matrix_sync(cp, acc[i][j], Nd, wmma::mem_row_major);
        }
}

// ===========================================================================
// converters
// ===========================================================================
__global__ void cvt_fp16_4(const float* __restrict__ s,
                           __half* __restrict__ d, int n4)
{
    int i = blockIdx.x * blockDim.x + threadIdx.x;
    if (i < n4) {
        float4 v = ((const float4*)s)[i];
        __half2* dp = (__half2*)(d) + 2 * i;
        dp[0] = __floats2half2_rn(v.x, v.y);
        dp[1] = __floats2half2_rn(v.z, v.w);
    }
}

__global__ void cvt_hilo4(const float* __restrict__ s,
                          __nv_bfloat16* __restrict__ hi,
                          __nv_bfloat16* __restrict__ lo, int n4)
{
    int i = blockIdx.x * blockDim.x + threadIdx.x;
    if (i < n4) {
        float4 v = ((const float4*)s)[i];
        __nv_bfloat16 h0 = __float2bfloat16(v.x);
        __nv_bfloat16 h1 = __float2bfloat16(v.y);
        __nv_bfloat16 h2 = __float2bfloat16(v.z);
        __nv_bfloat16 h3 = __float2bfloat16(v.w);
        __nv_bfloat162* hp = (__nv_bfloat162*)(hi) + 2 * i;
        __nv_bfloat162* lp = (__nv_bfloat162*)(lo) + 2 * i;
        hp[0] = __nv_bfloat162(h0, h1);
        hp[1] = __nv_bfloat162(h2, h3);
        lp[0] = __nv_bfloat162(__float2bfloat16(v.x - __bfloat162float(h0)),
                               __float2bfloat16(v.y - __bfloat162float(h1)));
        lp[1] = __nv_bfloat162(__float2bfloat16(v.z - __bfloat162float(h2)),
                               __float2bfloat16(v.w - __bfloat162float(h3)));
    }
}

// ===========================================================================
// RoPE + split qkv -> Q/K (roped), V, fp16 in [b,h,t,d]
// ===========================================================================
__global__ void rope_split(const float* __restrict__ qkv,
                           const float* __restrict__ cosp,
                           const float* __restrict__ sinp)
{
    int idx = blockIdx.x * blockDim.x + threadIdx.x;
    int dd = idx & 31;
    int rest = idx >> 5;
    int t = rest & (kT - 1);
    rest >>= 11;
    int h = rest & (kH - 1);
    int b = rest >> 4;

    int base = (b * kT + t) * kNQKV + h * kD;
    float c  = cosp[t * 32 + dd];
    float sn = sinp[t * 32 + dd];

    float q1 = qkv[base + dd];
    float q2 = qkv[base + 32 + dd];
    float k1 = qkv[base + kC + dd];
    float k2 = qkv[base + kC + 32 + dd];
    float v1 = qkv[base + 2 * kC + dd];
    float v2 = qkv[base + 2 * kC + 32 + dd];

    int o = ((b * kH + h) * kT + t) * kD + dd;
    g_qf[o]      = __float2half_rn(q1 * c - q2 * sn);
    g_qf[o + 32] = __float2half_rn(q2 * c + q1 * sn);
    g_kf[o]      = __float2half_rn(k1 * c - k2 * sn);
    g_kf[o + 32] = __float2half_rn(k2 * c + k1 * sn);
    g_vf[o]      = __float2half_rn(v1);
    g_vf[o + 32] = __float2half_rn(v2);
}

// ===========================================================================
// FP16 WMMA flash attention: 64 q/block, 64-key tiles, 8 warps,
// cp.async double-buffered K/V (prefetch-ahead-1).
// S = Q@K^T (single fp16 product) -> smem -> masked exp (max-free) ->
// P fp16 -> O += P@V. O frags persist; epilogue writes bf16 hi/lo.
// smem: Q[64][72] + K[2][64][72] + V[2][64][72] + Pb[64][72] (half)
//       + Ps[64][68] f32 + lp[4][64] f32  = 73728 B -> 2 CTA/SM.
// ===========================================================================
constexpr int kHT = 64 * 72;                 // half-tile elems
constexpr int kAttnSmem = (6 * kHT) * 2 + 64 * 68 * 4 + 256 * 4; // 73728

__global__ __launch_bounds__(256, 2) void flash_fp16()
{
    extern __shared__ char smraw[];
    __half* Qs = (__half*)smraw;             // [64][72]
    __half* Ks = Qs + kHT;                   // [2][64][72]
    __half* Vs = Ks + 2 * kHT;               // [2][64][72]
    __half* Pb = Vs + 2 * kHT;               // [64][72]
    float* Ps = (float*)(Pb + kHT);          // [64][68]
    float* lp = Ps + 64 * 68;                // [4][64]

    const int tid = threadIdx.x, warp = tid >> 5;
    const int wm = warp & 3, wn = warp >> 2;
    const int bh = blockIdx.y;
    const int q0 = blockIdx.x * 64;
    const float SCL2E = 0.125f * 1.4426950408889634f;

    const size_t hb = (size_t)bh * kT * kD;
    const __half* Kg = g_kf + hb;
    const __half* Vg = g_vf + hb;

    lp[tid] = 0.f;
    // stage Q (plain loads, once): 64x64 half = 512 x 8-half chunks
#pragma unroll
    for (int s = 0; s < 2; s++) {
        int idx = tid + s * 256;
        int r = idx >> 3, c8 = (idx & 7) * 8;
        *(uint4*)&Qs[r * 72 + c8] = *(const uint4*)(g_qf + hb + (q0 + r) * kD + c8);
    }

    const int ntiles = blockIdx.x + 1;

    // K/V staging via cp.async: one group per tile (K + V), 4 chunks/thread
    auto issue_kv = [&](int kt) {
        int buf = kt & 1;
#pragma unroll
        for (int s = 0; s < 2; s++) {
            int idx = tid + s * 256;
            int r = idx >> 3, c8 = (idx & 7) * 8;
            size_t g = (size_t)(kt * 64 + r) * kD + c8;
            cp_async16(&Ks[buf * kHT + r * 72 + c8], Kg + g);
            cp_async16(&Vs[buf * kHT + r * 72 + c8], Vg + g);
        }
        cp_commit();
    };

    issue_kv(0);

    wmma::fragment<wmma::accumulator, 16, 16, 16, float> oacc[2];
#pragma unroll
    for (int j = 0; j < 2; j++) wmma::fill_fragment(oacc[j], 0.f);

    for (int kt = 0; kt < ntiles; kt++) {
        const int kb = kt * 64;
        const int buf = kt & 1;
        __syncthreads();                       // prev PV readers done with buf^1
        if (kt + 1 < ntiles) { issue_kv(kt + 1); cp_wait1(); }
        else                 { cp_wait0(); }
        __syncthreads();                       // tile kt K/V visible to all

        // ---- S = Q @ K^T (single fp16 product, warp tile 16x32)
        wmma::fragment<wmma::accumulator, 16, 16, 16, float> sacc[2];
#pragma unroll
        for (int j = 0; j < 2; j++) wmma::fill_fragment(sacc[j], 0.f);
#pragma unroll
        for (int ks = 0; ks < 4; ks++) {
            wmma::fragment<wmma::matrix_a, 16, 16, 16, __half,
                           wmma::row_major> af;
            wmma::load_matrix_sync(af, &Qs[(wm * 16) * 72 + ks * 16], 72);
#pragma unroll
            for (int j = 0; j < 2; j++) {
                wmma::fragment<wmma::matrix_b, 16, 16, 16, __half,
                               wmma::col_major> bf;
                wmma::load_matrix_sync(
                    bf, &Ks[buf * kHT + (wn * 32 + j * 16) * 72 + ks * 16], 72);
                wmma::mma_sync(sacc[j], af, bf, sacc[j]);
            }
        }
#pragma unroll
        for (int j = 0; j < 2; j++)
            wmma::store_matrix_sync(&Ps[(wm * 16) * 68 + wn * 32 + j * 16],
                                    sacc[j], 68, wmma::mem_row_major);
        __syncthreads();

        // ---- masked exp (max-free), row-partial normalizer, P -> fp16
        {
            int r = tid >> 2, g = tid & 3;
            int qpos = q0 + r;
            float lsum = 0.f;
#pragma unroll
            for (int i = 0; i < 16; i++) {
                int c = g * 16 + i;
                float p = fast_exp2(Ps[r * 68 + c] * SCL2E);
                if (kb + c > qpos) p = 0.f;
                lsum += p;
                Pb[r * 72 + c] = __float2half_rn(p);
            }
            lp[g * 64 + r] += lsum;
        }
        __syncthreads();

        // ---- O += P @ V (single fp16 product)
#pragma unroll
        for (int ks = 0; ks < 4; ks++) {
            wmma::fragment<wmma::matrix_a, 16, 16, 16, __half,
                           wmma::row_major> af;
            wmma::load_matrix_sync(af, &Pb[(wm * 16) * 72 + ks * 16], 72);
#pragma unroll
            for (int j = 0; j < 2; j++) {
                wmma::fragment<wmma::matrix_b, 16, 16, 16, __half,
                               wmma::row_major> bf;
                wmma::load_matrix_sync(
                    bf, &Vs[buf * kHT + (ks * 16) * 72 + wn * 32 + j * 16], 72);
                wmma::mma_sync(oacc[j], af, bf, oacc[j]);
            }
        }
    }

    // ---- epilogue: O -> smem, normalize rows, write bf16 hi/lo
    __syncthreads();
#pragma unroll
    for (int j = 0; j < 2; j++)
        wmma::store_matrix_sync(&Ps[(wm * 16) * 68 + wn * 32 + j * 16],
                                oacc[j], 68, wmma::mem_row_major);
    __syncthreads();
    {
        int r = tid >> 2, g = tid & 3;
        float lrow = lp[r] + lp[64 + r] + lp[128 + r] + lp[192 + r];
        float inv = 1.f / lrow;
        const int b = bh >> 4, h = bh & 15;
        size_t base = (size_t)(b * kT + q0 + r) * kC + h * kD;
#pragma unroll
        for (int i = 0; i < 16; i++) {
            int c = g * 16 + i;
            float v = Ps[r * 68 + c] * inv;
            __nv_bfloat16 hv = __float2bfloat16(v);
            g_ath[base + c] = hv;
            g_atl[base + c] = __float2bfloat16(v - __bfloat162float(hv));
        }
    }
}

// ===========================================================================
extern "C" void kernel_launch(void* const* d_in, const int* in_sizes, int n_in,
                              void* d_out, int out_size)
{
    const float* x    = (const float*)d_in[0];
    const float* cosp = (const float*)d_in[1];
    const float* sinp = (const float*)d_in[2];
    // d_in[3] = mask (implicit causal)
    const float* Wqkv = (const float*)d_in[4];
    const float* Wout = (const float*)d_in[5];
    float* out = (float*)d_out;

    float* pqkv;
    __half *pxf, *pwqf;
    __nv_bfloat16 *path, *patl, *pwoh, *pwol;
    cudaGetSymbolAddress((void**)&pqkv, g_qkv);
    cudaGetSymbolAddress((void**)&pxf, g_xf);
    cudaGetSymbolAddress((void**)&pwqf, g_wqf);
    cudaGetSymbolAddress((void**)&path, g_ath);
    cudaGetSymbolAddress((void**)&patl, g_atl);
    cudaGetSymbolAddress((void**)&pwoh, g_woh);
    cudaGetSymbolAddress((void**)&pwol, g_wol);

    cudaFuncSetAttribute(gemm_wmma_fp16,
                         cudaFuncAttributeMaxDynamicSharedMemorySize, kGemmSmem16);
    cudaFuncSetAttribute(gemm_wmma_split,
                         cudaFuncAttributeMaxDynamicSharedMemorySize, kGemmSmemBf);
    cudaFuncSetAttribute(flash_fp16,
                         cudaFuncAttributeMaxDynamicSharedMemorySize, kAttnSmem);

    // 1. convert QKV-GEMM inputs to fp16, out-proj weights to bf16 hi/lo
    cvt_fp16_4<<<(kM * kC / 4 + 255) / 256, 256>>>(x, pxf, kM * kC / 4);
    cvt_fp16_4<<<(kNQKV * kC / 4 + 255) / 256, 256>>>(Wqkv, pwqf, kNQKV * kC / 4);
    cvt_hilo4<<<(kC * kC / 4 + 255) / 256, 256>>>(Wout, pwoh, pwol, kC * kC / 4);

    // 2. QKV projection (single-pass fp16 WMMA)
    gemm_wmma_fp16<<<dim3(kNQKV / 128, kM / 128), 256, kGemmSmem16>>>(
        pxf, pwqf, pqkv, kNQKV, kC);

    // 3. RoPE + head split -> fp16 Q/K/V
    rope_split<<<(kBH * kT * 32) / 256, 256>>>(pqkv, cosp, sinp);

    // 4. fp16 WMMA causal attention (writes bf16 hi/lo directly)
    flash_fp16<<<dim3(kT / 64, kBH), 256, kAttnSmem>>>();

    // 5. output projection (3-pass split-bf16 — precision-critical)
    gemm_wmma_split<<<dim3(kC / 128, kM / 128), 256, kGemmSmemBf>>>(
        path, patl, pwoh, pwol, out, kC, kC);
}

// round 17
// speedup vs baseline: 2.1202x; 2.1202x over previous
#include <cuda_runtime.h>
#include <cuda_bf16.h>
#include <cuda_fp16.h>
#include <mma.h>
#include <cstdint>

using namespace nvcuda;

// Problem constants
constexpr int kB = 2;
constexpr int kT = 2048;
constexpr int kC = 1024;
constexpr int kH = 16;
constexpr int kD = 64;
constexpr int kM = kB * kT;        // 4096
constexpr int kNQKV = 3 * kC;      // 3072
constexpr int kBH = kB * kH;       // 32

// Scratch (static device globals — no allocation allowed)
__device__ float g_qkv[kM * kNQKV];
__device__ __half g_qf[kBH * kT * kD];
__device__ __half g_kf[kBH * kT * kD];
__device__ __half g_vf[kBH * kT * kD];
// fp16 QKV-GEMM operands
__device__ __half g_xf[kM * kC];
__device__ __half g_wqf[kNQKV * kC];
// split-bf16 out-proj operands
__device__ __nv_bfloat16 g_ath[kM * kC], g_atl[kM * kC];
__device__ __nv_bfloat16 g_woh[kC * kC], g_wol[kC * kC];

// ===========================================================================
// helpers
// ===========================================================================
__device__ __forceinline__ uint32_t smem_u32(const void* p) {
    uint32_t a;
    asm("{ .reg .u64 t; cvta.to.shared.u64 t, %1; cvt.u32.u64 %0, t; }"
        : "=r"(a) : "l"(p));
    return a;
}
__device__ __forceinline__ void cp_async16(void* sdst, const void* gsrc) {
    asm volatile("cp.async.cg.shared.global [%0], [%1], 16;"
                 :: "r"(smem_u32(sdst)), "l"(gsrc) : "memory");
}
__device__ __forceinline__ void cp_commit() {
    asm volatile("cp.async.commit_group;" ::: "memory");
}
__device__ __forceinline__ void cp_wait0() {
    asm volatile("cp.async.wait_group 0;" ::: "memory");
}
__device__ __forceinline__ void cp_wait1() {
    asm volatile("cp.async.wait_group 1;" ::: "memory");
}
__device__ __forceinline__ void cp_wait2() {
    asm volatile("cp.async.wait_group 2;" ::: "memory");
}
__device__ __forceinline__ float fast_exp2(float x) {
    float y;
    asm("ex2.approx.ftz.f32 %0, %1;" : "=f"(y) : "f"(x));
    return y;
}
__device__ __forceinline__ void ldsm_x4(uint32_t& r0, uint32_t& r1,
                                        uint32_t& r2, uint32_t& r3, uint32_t a) {
    asm volatile("ldmatrix.sync.aligned.m8n8.x4.shared.b16 {%0,%1,%2,%3}, [%4];"
                 : "=r"(r0), "=r"(r1), "=r"(r2), "=r"(r3) : "r"(a));
}
__device__ __forceinline__ void ldsm_x2(uint32_t& r0, uint32_t& r1, uint32_t a) {
    asm volatile("ldmatrix.sync.aligned.m8n8.x2.shared.b16 {%0,%1}, [%2];"
                 : "=r"(r0), "=r"(r1) : "r"(a));
}
__device__ __forceinline__ void ldsm_x2t(uint32_t& r0, uint32_t& r1, uint32_t a) {
    asm volatile("ldmatrix.sync.aligned.m8n8.x2.trans.shared.b16 {%0,%1}, [%2];"
                 : "=r"(r0), "=r"(r1) : "r"(a));
}
__device__ __forceinline__ void mma16816(float* d, const uint32_t* a,
                                         uint32_t b0, uint32_t b1) {
    asm volatile(
        "mma.sync.aligned.m16n8k16.row.col.f32.f16.f16.f32 "
        "{%0,%1,%2,%3}, {%4,%5,%6,%7}, {%8,%9}, {%0,%1,%2,%3};"
        : "+f"(d[0]), "+f"(d[1]), "+f"(d[2]), "+f"(d[3])
        : "r"(a[0]), "r"(a[1]), "r"(a[2]), "r"(a[3]), "r"(b0), "r"(b1));
}
__device__ __forceinline__ uint32_t pack_half2(float a, float b) {
    __half2 h = __floats2half2_rn(a, b);
    return *(uint32_t*)&h;
}

// ===========================================================================
// Single-pass FP16 GEMM-NT via WMMA (QKV projection). Round-13 proven.
// ===========================================================================
constexpr int kLds = 40;
constexpr int kStageElems = 2 * 128 * kLds;
constexpr int kGemmSmem16 = 4 * kStageElems * 2;

__global__ __launch_bounds__(256) void gemm_wmma_fp16(
    const __half* __restrict__ A, const __half* __restrict__ Bm,
    float* __restrict__ Cm, int Nd, int Kd)
{
    extern __shared__ __half smh[];

    const int tid = threadIdx.x;
    const int warp = tid >> 5;
    const int wm = warp & 3;
    const int wn = warp >> 2;
    const int row0 = blockIdx.y * 128;
    const int col0 = blockIdx.x * 128;

    const int nchunk = Kd >> 5;

    auto issue = [&](int it) {
        const int kc = it << 5;
        __half* As = smh + (it & 3) * kStageElems;
        __half* Bs = As + 128 * kLds;
#pragma unroll
        for (int s = 0; s < 2; s++) {
            int idx = tid + s * 256;
            int r = idx >> 2;
            int c8 = (idx & 3) * 8;
            cp_async16(&As[r * kLds + c8], A + (size_t)(row0 + r) * Kd + kc + c8);
            cp_async16(&Bs[r * kLds + c8], Bm + (size_t)(col0 + r) * Kd + kc + c8);
        }
    };

    wmma::fragment<wmma::accumulator, 16, 16, 16, float> acc[2][4];
#pragma unroll
    for (int i = 0; i < 2; i++)
#pragma unroll
        for (int j = 0; j < 4; j++)
            wmma::fill_fragment(acc[i][j], 0.f);

    issue(0); cp_commit();
    issue(1); cp_commit();
    issue(2); cp_commit();

    for (int it = 0; it < nchunk; it++) {
        cp_wait2();
        __syncthreads();
        if (it + 3 < nchunk) issue(it + 3);
        cp_commit();

        const __half* As = smh + (it & 3) * kStageElems;
        const __half* Bs = As + 128 * kLds;
#pragma unroll
        for (int k2 = 0; k2 < 2; k2++) {
            wmma::fragment<wmma::matrix_a, 16, 16, 16, __half,
                           wmma::row_major> af[2];
            wmma::fragment<wmma::matrix_b, 16, 16, 16, __half,
                           wmma::col_major> bf[4];
#pragma unroll
            for (int i = 0; i < 2; i++)
                wmma::load_matrix_sync(
                    af[i], &As[(wm * 32 + i * 16) * kLds + k2 * 16], kLds);
#pragma unroll
            for (int j = 0; j < 4; j++)
                wmma::load_matrix_sync(
                    bf[j], &Bs[(wn * 64 + j * 16) * kLds + k2 * 16], kLds);
#pragma unroll
            for (int i = 0; i < 2; i++)
#pragma unroll
                for (int j = 0; j < 4; j++)
                    wmma::mma_sync(acc[i][j], af[i], bf[j], acc[i][j]);
        }
    }

#pragma unroll
    for (int i = 0; i < 2; i++)
#pragma unroll
        for (int j = 0; j < 4; j++) {
            float* cp = Cm + (size_t)(row0 + wm * 32 + i * 16) * Nd
                           + col0 + wn * 64 + j * 16;
            wmma::store_matrix_sync(cp, acc[i][j], Nd, wmma::mem_row_major);
        }
}

// ===========================================================================
// 3-pass split-bf16 GEMM-NT via WMMA (round-5 proven) — out-projection.
// ===========================================================================
constexpr int kGemmSmemBf = 4 * kStageElems * 2;

__global__ __launch_bounds__(256) void gemm_wmma_split(
    const __nv_bfloat16* __restrict__ Ah, const __nv_bfloat16* __restrict__ Al,
    const __nv_bfloat16* __restrict__ Bh, const __nv_bfloat16* __restrict__ Bl,
    float* __restrict__ Cm, int Nd, int Kd)
{
    extern __shared__ __nv_bfloat16 sm[];

    const int tid = threadIdx.x;
    const int warp = tid >> 5;
    const int wm = warp & 3;
    const int wn = warp >> 2;
    const int row0 = blockIdx.y * 128;
    const int col0 = blockIdx.x * 128;

    const int nchunk = Kd >> 5;
    const int total = 3 * nchunk;

    auto issue = [&](int it) {
        const int pass = it / nchunk;
        const int kc = (it - pass * nchunk) << 5;
        const __nv_bfloat16* Ap = (pass == 2) ? Al : Ah;
        const __nv_bfloat16* Bp = (pass == 1) ? Bl : Bh;
        __nv_bfloat16* As = sm + (it & 3) * kStageElems;
        __nv_bfloat16* Bs = As + 128 * kLds;
#pragma unroll
        for (int s = 0; s < 2; s++) {
            int idx = tid + s * 256;
            int r = idx >> 2;
            int c8 = (idx & 3) * 8;
            cp_async16(&As[r * kLds + c8], Ap + (size_t)(row0 + r) * Kd + kc + c8);
            cp_async16(&Bs[r * kLds + c8], Bp + (size_t)(col0 + r) * Kd + kc + c8);
        }
    };

    wmma::fragment<wmma::accumulator, 16, 16, 16, float> acc[2][4];
#pragma unroll
    for (int i = 0; i < 2; i++)
#pragma unroll
        for (int j = 0; j < 4; j++)
            wmma::fill_fragment(acc[i][j], 0.f);

    issue(0); cp_commit();
    issue(1); cp_commit();
    issue(2); cp_commit();

    for (int it = 0; it < total; it++) {
        cp_wait2();
        __syncthreads();
        if (it + 3 < total) issue(it + 3);
        cp_commit();

        const __nv_bfloat16* As = sm + (it & 3) * kStageElems;
        const __nv_bfloat16* Bs = As + 128 * kLds;
#pragma unroll
        for (int k2 = 0; k2 < 2; k2++) {
            wmma::fragment<wmma::matrix_a, 16, 16, 16, __nv_bfloat16,
                           wmma::row_major> af[2];
            wmma::fragment<wmma::matrix_b, 16, 16, 16, __nv_bfloat16,
                           wmma::col_major> bf[4];
#pragma unroll
            for (int i = 0; i < 2; i++)
                wmma::load_matrix_sync(
                    af[i], &As[(wm * 32 + i * 16) * kLds + k2 * 16], kLds);
#pragma unroll
            for (int j = 0; j < 4; j++)
                wmma::load_matrix_sync(
                    bf[j], &Bs[(wn * 64 + j * 16) * kLds + k2 * 16], kLds);
#pragma unroll
            for (int i = 0; i < 2; i++)
#pragma unroll
                for (int j = 0; j < 4; j++)
                    wmma::mma_sync(acc[i][j], af[i], bf[j], acc[i][j]);
        }
    }

#pragma unroll
    for (int i = 0; i < 2; i++)
#pragma unroll
        for (int j = 0; j < 4; j++) {
            float* cp = Cm + (size_t)(row0 + wm * 32 + i * 16) * Nd
                           + col0 + wn * 64 + j * 16;
            wmma::store_matrix_sync(cp, acc[i][j], Nd, wmma::mem_row_major);
        }
}

// ===========================================================================
// converters
// ===========================================================================
__global__ void cvt_fp16_4(const float* __restrict__ s,
                           __half* __restrict__ d, int n4)
{
    int i = blockIdx.x * blockDim.x + threadIdx.x;
    if (i < n4) {
        float4 v = ((const float4*)s)[i];
        __half2* dp = (__half2*)(d) + 2 * i;
        dp[0] = __floats2half2_rn(v.x, v.y);
        dp[1] = __floats2half2_rn(v.z, v.w);
    }
}

__global__ void cvt_hilo4(const float* __restrict__ s,
                          __nv_bfloat16* __restrict__ hi,
                          __nv_bfloat16* __restrict__ lo, int n4)
{
    int i = blockIdx.x * blockDim.x + threadIdx.x;
    if (i < n4) {
        float4 v = ((const float4*)s)[i];
        __nv_bfloat16 h0 = __float2bfloat16(v.x);
        __nv_bfloat16 h1 = __float2bfloat16(v.y);
        __nv_bfloat16 h2 = __float2bfloat16(v.z);
        __nv_bfloat16 h3 = __float2bfloat16(v.w);
        __nv_bfloat162* hp = (__nv_bfloat162*)(hi) + 2 * i;
        __nv_bfloat162* lp = (__nv_bfloat162*)(lo) + 2 * i;
        hp[0] = __nv_bfloat162(h0, h1);
        hp[1] = __nv_bfloat162(h2, h3);
        lp[0] = __nv_bfloat162(__float2bfloat16(v.x - __bfloat162float(h0)),
                               __float2bfloat16(v.y - __bfloat162float(h1)));
        lp[1] = __nv_bfloat162(__float2bfloat16(v.z - __bfloat162float(h2)),
                               __float2bfloat16(v.w - __bfloat162float(h3)));
    }
}

// ===========================================================================
// RoPE + split qkv -> Q/K (roped), V, fp16 in [b,h,t,d]
// ===========================================================================
__global__ void rope_split(const float* __restrict__ qkv,
                           const float* __restrict__ cosp,
                           const float* __restrict__ sinp)
{
    int idx = blockIdx.x * blockDim.x + threadIdx.x;
    int dd = idx & 31;
    int rest = idx >> 5;
    int t = rest & (kT - 1);
    rest >>= 11;
    int h = rest & (kH - 1);
    int b = rest >> 4;

    int base = (b * kT + t) * kNQKV + h * kD;
    float c  = cosp[t * 32 + dd];
    float sn = sinp[t * 32 + dd];

    float q1 = qkv[base + dd];
    float q2 = qkv[base + 32 + dd];
    float k1 = qkv[base + kC + dd];
    float k2 = qkv[base + kC + 32 + dd];
    float v1 = qkv[base + 2 * kC + dd];
    float v2 = qkv[base + 2 * kC + 32 + dd];

    int o = ((b * kH + h) * kT + t) * kD + dd;
    g_qf[o]      = __float2half_rn(q1 * c - q2 * sn);
    g_qf[o + 32] = __float2half_rn(q2 * c + q1 * sn);
    g_kf[o]      = __float2half_rn(k1 * c - k2 * sn);
    g_kf[o + 32] = __float2half_rn(k2 * c + k1 * sn);
    g_vf[o]      = __float2half_rn(v1);
    g_vf[o + 32] = __float2half_rn(v2);
}

// ===========================================================================
// Register-resident FA2 attention via raw mma.sync.m16n8k16.
// q-block 128, 8 warps x 16 rows, each warp owns all 64 keys of a tile ->
// softmax fully warp-local (no smem S/P, no per-tile block syncs beyond
// staging). S C-frags -> in-register mask/exp/normalizer -> packed directly
// into PV A-frags (standard FA2 C->A layout identity). K via ldmatrix.x2,
// V via ldmatrix.x2.trans, cp.async double-buffered K/V.
// smem: Q[128][72] + K[2][64][72] + V[2][64][72] half = 55296 B -> 2 CTA/SM.
// ===========================================================================
constexpr int kAttnSmem = (128 * 72 + 2 * 64 * 72 + 2 * 64 * 72) * 2;

__global__ __launch_bounds__(256, 2) void flash_reg()
{
    extern __shared__ char smraw[];
    __half* Qs = (__half*)smraw;             // [128][72]
    __half* Ks = Qs + 128 * 72;              // [2][64][72]
    __half* Vs = Ks + 2 * 64 * 72;           // [2][64][72]

    const int tid = threadIdx.x, warp = tid >> 5, lane = tid & 31;
    const int gid = lane >> 2, tig = lane & 3;
    const int bh = blockIdx.y;
    const int q0 = blockIdx.x * 128;
    const float SCL2E = 0.125f * 1.4426950408889634f;

    const size_t hb = (size_t)bh * kT * kD;
    const __half* Qg = g_qf + hb;
    const __half* Kg = g_kf + hb;
    const __half* Vg = g_vf + hb;

    const int ntiles = 2 * blockIdx.x + 2;

    auto issue_kv = [&](int kt) {
        int buf = kt & 1;
#pragma unroll
        for (int s = 0; s < 2; s++) {
            int idx = tid + s * 256;
            int r = idx >> 3, c8 = (idx & 7) * 8;
            size_t g = (size_t)(kt * 64 + r) * kD + c8;
            cp_async16(&Ks[(buf * 64 + r) * 72 + c8], Kg + g);
            cp_async16(&Vs[(buf * 64 + r) * 72 + c8], Vg + g);
        }
        cp_commit();
    };

    issue_kv(0);

    // stage Q (128x64 halves, 4 chunks/thread)
#pragma unroll
    for (int s = 0; s < 4; s++) {
        int idx = tid + s * 256;
        int r = idx >> 3, c8 = (idx & 7) * 8;
        *(uint4*)&Qs[r * 72 + c8] = *(const uint4*)(Qg + (size_t)(q0 + r) * kD + c8);
    }
    __syncthreads();

    // Q A-frags (persist across all tiles): qa[kd][0..3]
    uint32_t qa[4][4];
    {
        int qrow = warp * 16 + (lane & 15);
        int qcol8 = (lane & 16) ? 8 : 0;
#pragma unroll
        for (int kd = 0; kd < 4; kd++)
            ldsm_x4(qa[kd][0], qa[kd][1], qa[kd][2], qa[kd][3],
                    smem_u32(&Qs[qrow * 72 + kd * 16 + qcol8]));
    }

    float oacc[8][4];
#pragma unroll
    for (int j = 0; j < 8; j++)
#pragma unroll
        for (int r = 0; r < 4; r++) oacc[j][r] = 0.f;
    float l0 = 0.f, l1 = 0.f;

    const int kl = lane & 7;
    const int ksel8 = (lane & 8) ? 8 : 0;    // K ldsm: col +8 for b1 lanes
    const int vkrow = lane & 15;             // V ldsm.trans: 16 k-rows

    for (int kt = 0; kt < ntiles; kt++) {
        const int kb = kt * 64;
        const int buf = kt & 1;
        if (kt + 1 < ntiles) { issue_kv(kt + 1); cp_wait1(); }
        else                 { cp_wait0(); }
        __syncthreads();

        // ---- S = Q @ K^T  (8 n8-tiles over 64 keys, 4 k16 chunks over d)
        float S[8][4];
#pragma unroll
        for (int j = 0; j < 8; j++)
#pragma unroll
            for (int r = 0; r < 4; r++) S[j][r] = 0.f;
#pragma unroll
        for (int kd = 0; kd < 4; kd++) {
#pragma unroll
            for (int j = 0; j < 8; j++) {
                uint32_t b0, b1;
                ldsm_x2(b0, b1, smem_u32(
                    &Ks[(buf * 64 + j * 8 + kl) * 72 + kd * 16 + ksel8]));
                mma16816(S[j], qa[kd], b0, b1);
            }
        }

        // ---- mask + exp (max-free) + lane-partial normalizer, in registers
        const int rowb = q0 + warp * 16 + gid;
        const bool need_mask = (kb + 63 > q0 + warp * 16);
#pragma unroll
        for (int j = 0; j < 8; j++) {
#pragma unroll
            for (int r = 0; r < 4; r++) {
                float p = fast_exp2(S[j][r] * SCL2E);
                if (need_mask) {
                    int col = kb + j * 8 + 2 * tig + (r & 1);
                    int row = rowb + ((r >= 2) ? 8 : 0);
                    if (col > row) p = 0.f;
                }
                S[j][r] = p;
                if (r < 2) l0 += p; else l1 += p;
            }
        }

        // ---- pack P into PV A-frags (FA2 C->A identity, in-thread)
        uint32_t pa[4][4];
#pragma unroll
        for (int t = 0; t < 4; t++) {
            pa[t][0] = pack_half2(S[2 * t][0],     S[2 * t][1]);
            pa[t][1] = pack_half2(S[2 * t][2],     S[2 * t][3]);
            pa[t][2] = pack_half2(S[2 * t + 1][0], S[2 * t + 1][1]);
            pa[t][3] = pack_half2(S[2 * t + 1][2], S[2 * t + 1][3]);
        }

        // ---- O += P @ V  (4 k16 chunks over keys, 8 n8-tiles over d)
#pragma unroll
        for (int t = 0; t < 4; t++) {
#pragma unroll
            for (int j = 0; j < 8; j++) {
                uint32_t b0, b1;
                ldsm_x2t(b0, b1, smem_u32(
                    &Vs[(buf * 64 + t * 16 + vkrow) * 72 + j * 8]));
                mma16816(oacc[j], pa[t], b0, b1);
            }
        }
        __syncthreads();   // readers done before next issue overwrites buf^1
    }

    // ---- normalizers: reduce over the 4 lanes of each row group
    l0 += __shfl_xor_sync(0xffffffffu, l0, 1);
    l0 += __shfl_xor_sync(0xffffffffu, l0, 2);
    l1 += __shfl_xor_sync(0xffffffffu, l1, 1);
    l1 += __shfl_xor_sync(0xffffffffu, l1, 2);
    float inv0 = 1.f / l0, inv1 = 1.f / l1;

    // ---- epilogue: write bf16 hi/lo directly from fragments
    const int b = bh >> 4, h = bh & 15;
    const int grow0 = q0 + warp * 16 + gid;
    size_t base0 = (size_t)(b * kT + grow0) * kC + h * kD + 2 * tig;
    size_t base1 = base0 + (size_t)8 * kC;
#pragma unroll
    for (int j = 0; j < 8; j++) {
        float v0 = oacc[j][0] * inv0, v1 = oacc[j][1] * inv0;
        float v2 = oacc[j][2] * inv1, v3 = oacc[j][3] * inv1;
        __nv_bfloat16 h0 = __float2bfloat16(v0), h1 = __float2bfloat16(v1);
        __nv_bfloat16 h2 = __float2bfloat16(v2), h3 = __float2bfloat16(v3);
        *(__nv_bfloat162*)&g_ath[base0 + j * 8] = __nv_bfloat162(h0, h1);
        *(__nv_bfloat162*)&g_atl[base0 + j * 8] = __nv_bfloat162(
            __float2bfloat16(v0 - __bfloat162float(h0)),
            __float2bfloat16(v1 - __bfloat162float(h1)));
        *(__nv_bfloat162*)&g_ath[base1 + j * 8] = __nv_bfloat162(h2, h3);
        *(__nv_bfloat162*)&g_atl[base1 + j * 8] = __nv_bfloat162(
            __float2bfloat16(v2 - __bfloat162float(h2)),
            __float2bfloat16(v3 - __bfloat162float(h3)));
    }
}

// ===========================================================================
extern "C" void kernel_launch(void* const* d_in, const int* in_sizes, int n_in,
                              void* d_out, int out_size)
{
    const float* x    = (const float*)d_in[0];
    const float* cosp = (const float*)d_in[1];
    const float* sinp = (const float*)d_in[2];
    // d_in[3] = mask (implicit causal)
    const float* Wqkv = (const float*)d_in[4];
    const float* Wout = (const float*)d_in[5];
    float* out = (float*)d_out;

    float* pqkv;
    __half *pxf, *pwqf;
    __nv_bfloat16 *path, *patl, *pwoh, *pwol;
    cudaGetSymbolAddress((void**)&pqkv, g_qkv);
    cudaGetSymbolAddress((void**)&pxf, g_xf);
    cudaGetSymbolAddress((void**)&pwqf, g_wqf);
    cudaGetSymbolAddress((void**)&path, g_ath);
    cudaGetSymbolAddress((void**)&patl, g_atl);
    cudaGetSymbolAddress((void**)&pwoh, g_woh);
    cudaGetSymbolAddress((void**)&pwol, g_wol);

    cudaFuncSetAttribute(gemm_wmma_fp16,
                         cudaFuncAttributeMaxDynamicSharedMemorySize, kGemmSmem16);
    cudaFuncSetAttribute(gemm_wmma_split,
                         cudaFuncAttributeMaxDynamicSharedMemorySize, kGemmSmemBf);
    cudaFuncSetAttribute(flash_reg,
                         cudaFuncAttributeMaxDynamicSharedMemorySize, kAttnSmem);

    // 1. convert QKV-GEMM inputs to fp16, out-proj weights to bf16 hi/lo
    cvt_fp16_4<<<(kM * kC / 4 + 255) / 256, 256>>>(x, pxf, kM * kC / 4);
    cvt_fp16_4<<<(kNQKV * kC / 4 + 255) / 256, 256>>>(Wqkv, pwqf, kNQKV * kC / 4);
    cvt_hilo4<<<(kC * kC / 4 + 255) / 256, 256>>>(Wout, pwoh, pwol, kC * kC / 4);

    // 2. QKV projection (single-pass fp16 WMMA)
    gemm_wmma_fp16<<<dim3(kNQKV / 128, kM / 128), 256, kGemmSmem16>>>(
        pxf, pwqf, pqkv, kNQKV, kC);

    // 3. RoPE + head split -> fp16 Q/K/V
    rope_split<<<(kBH * kT * 32) / 256, 256>>>(pqkv, cosp, sinp);

    // 4. register-resident FA2 attention (writes bf16 hi/lo directly)
    flash_reg<<<dim3(kT / 128, kBH), 256, kAttnSmem>>>();

    // 5. output projection (3-pass split-bf16 — precision-critical)
    gemm_wmma_split<<<dim3(kC / 128, kM / 128), 256, kGemmSmemBf>>>(
        path, patl, pwoh, pwol, out, kC, kC);
}